// round 6
// baseline (speedup 1.0000x reference)
#include <cuda_runtime.h>
#include <cstdint>

#define D_ 256
#define L_ 4
#define H_ 8
#define TM 32
#define NT 256
#define SXS 264  // padded smem row stride in floats

typedef unsigned long long ull;

// ---------------- interleaved-pair transposed weights ----------------
// g_WT2[mat][kp][o] is a 64-bit element = (W[2kp][o], W[2kp+1][o]),
// mats: 0=Wq 1=Wk 2=Wv 3=Wout 4=W1 5=W2 6=Wsave
__device__ ull g_WT2[7 * (D_ / 2) * D_];

__global__ void pack_weights_kernel(const float* __restrict__ Win,
                                    const float* __restrict__ Wout,
                                    const float* __restrict__ W1,
                                    const float* __restrict__ W2,
                                    const float* __restrict__ Wsave) {
    int idx = blockIdx.x * blockDim.x + threadIdx.x;
    if (idx >= 7 * (D_ / 2) * D_) return;
    int mat = idx / ((D_ / 2) * D_);
    int rem = idx - mat * ((D_ / 2) * D_);
    int kp = rem >> 8;
    int o = rem & 255;
    const float* src;
    switch (mat) {
        case 0: src = Win; break;
        case 1: src = Win + D_ * D_; break;
        case 2: src = Win + 2 * D_ * D_; break;
        case 3: src = Wout; break;
        case 4: src = W1; break;
        case 5: src = W2; break;
        default: src = Wsave; break;
    }
    float lo = src[o * D_ + 2 * kp];
    float hi = src[o * D_ + 2 * kp + 1];
    *reinterpret_cast<float2*>(&g_WT2[idx]) = make_float2(lo, hi);
}

// ---------------- packed f32x2 helpers (sm_103a) ----------------
__device__ __forceinline__ ull fma2(ull a, ull b, ull c) {
    ull r;
    asm("fma.rn.f32x2 %0, %1, %2, %3;" : "=l"(r) : "l"(a), "l"(b), "l"(c));
    return r;
}
__device__ __forceinline__ float f2sum(ull v) {
    float lo, hi;
    asm("mov.b64 {%0,%1}, %2;" : "=f"(lo), "=f"(hi) : "l"(v));
    return lo + hi;
}
__device__ __forceinline__ float wred(float v) {
#pragma unroll
    for (int s = 16; s > 0; s >>= 1) v += __shfl_xor_sync(0xffffffffu, v, s);
    return v;
}

// ---------------- register-tiled GEMV: 8 rows x 4 cols per thread ----------------
// A: tile base, row stride ldA floats (16B-aligned rows).
// WT2: interleaved-pair weights for this matrix.
// out[i][j] = sum_k A[ly*8+i][k] * W[k][col0+j].
// Inner loop: 4 LDG.128 + 8 LDS.128 + 64 FFMA2, zero packing ops.
__device__ __forceinline__ void gemv84(const float* __restrict__ A, int ldA,
                                       const ull* __restrict__ WT2, int col0,
                                       int ly, float out[8][4]) {
    ull acc[8][4];
#pragma unroll
    for (int i = 0; i < 8; i++)
#pragma unroll
        for (int j = 0; j < 4; j++) acc[i][j] = 0ull;
    const float* Arow = A + (size_t)(ly * 8) * ldA;
#pragma unroll 1
    for (int kc = 0; kc < D_; kc += 4) {
        const ull* Wp = WT2 + (size_t)(kc >> 1) * D_ + col0;
        ulonglong2 wA = __ldg(reinterpret_cast<const ulonglong2*>(Wp));
        ulonglong2 wB = __ldg(reinterpret_cast<const ulonglong2*>(Wp + 2));
        ulonglong2 wC = __ldg(reinterpret_cast<const ulonglong2*>(Wp + D_));
        ulonglong2 wD = __ldg(reinterpret_cast<const ulonglong2*>(Wp + D_ + 2));
        ull wp0[4] = {wA.x, wA.y, wB.x, wB.y};  // (k,k+1) for cols 0..3
        ull wp1[4] = {wC.x, wC.y, wD.x, wD.y};  // (k+2,k+3) for cols 0..3
#pragma unroll
        for (int i = 0; i < 8; i++) {
            ulonglong2 av =
                *reinterpret_cast<const ulonglong2*>(Arow + i * ldA + kc);
#pragma unroll
            for (int j = 0; j < 4; j++) {
                acc[i][j] = fma2(av.x, wp0[j], acc[i][j]);
                acc[i][j] = fma2(av.y, wp1[j], acc[i][j]);
            }
        }
    }
#pragma unroll
    for (int i = 0; i < 8; i++)
#pragma unroll
        for (int j = 0; j < 4; j++) out[i][j] = f2sum(acc[i][j]);
}

__device__ __forceinline__ void layernorm_inplace(float* sX, const float* __restrict__ g,
                                                  const float* __restrict__ b,
                                                  float* smu, float* srstd) {
    const int w = threadIdx.x >> 5, lane = threadIdx.x & 31;
#pragma unroll
    for (int k = 0; k < TM / 8; k++) {
        int m = w * (TM / 8) + k;
        float s = 0.f, s2 = 0.f;
#pragma unroll
        for (int i = lane; i < D_; i += 32) {
            float v = sX[m * SXS + i];
            s += v;
            s2 += v * v;
        }
        s = wred(s);
        s2 = wred(s2);
        if (lane == 0) {
            float mu = s * (1.f / D_);
            float var = s2 * (1.f / D_) - mu * mu;
            smu[m] = mu;
            srstd[m] = rsqrtf(var + 1e-5f);
        }
    }
    __syncthreads();
    const int o = threadIdx.x;
    float gg = __ldg(g + o), bb = __ldg(b + o);
#pragma unroll
    for (int m = 0; m < TM; m++)
        sX[m * SXS + o] = (sX[m * SXS + o] - smu[m]) * srstd[m] * gg + bb;
    __syncthreads();
}

constexpr int SMEM_FLOATS = 2 * TM * SXS   // sX, sB1 (sQ/sCtx/sH alias)
                            + TM * H_ * L_ // sAttn
                            + TM + TM      // smu, srstd
                            + TM + TM      // sValid, sSaved
                            + TM * L_;     // sKpm
constexpr int SMEM_BYTES = SMEM_FLOATS * 4;

__global__ void __launch_bounds__(NT, 2)
mb_kernel(const float* __restrict__ E, const float* __restrict__ scores,
          const float* __restrict__ bank, const unsigned int* __restrict__ maskw,
          const float* __restrict__ bsave, const float* __restrict__ bin,
          const float* __restrict__ bout, const float* __restrict__ b1,
          const float* __restrict__ b2, const float* __restrict__ g1,
          const float* __restrict__ be1, const float* __restrict__ g2,
          const float* __restrict__ be2, float* __restrict__ out_emb,
          float* __restrict__ out_bank, float* __restrict__ out_mask, int N) {
    extern __shared__ float sm[];
    float* sX = sm;                 // [TM][SXS]
    float* sB1 = sX + TM * SXS;     // [TM][SXS]  (aliases sQ / sCtx / sH)
    float* sAttn = sB1 + TM * SXS;  // [TM][H][L]
    float* smu = sAttn + TM * H_ * L_;
    float* srstd = smu + TM;
    float* sValid = srstd + TM;
    float* sSaved = sValid + TM;
    float* sKpm = sSaved + TM;      // [TM][L]

    const int tid = threadIdx.x;
    const int w = tid >> 5;          // warp == head == 32-col group
    const int lane = tid & 31;
    const int lx = lane & 7;         // col sub-group
    const int ly = lane >> 3;        // row group
    const int col0 = w * 32 + lx * 4;
    const long base = (long)blockIdx.x * TM;  // N % TM == 0 for this dataset

    const ull* WQt = g_WT2;
    const ull* WKt = g_WT2 + 1 * (D_ / 2) * D_;
    const ull* WVt = g_WT2 + 2 * (D_ / 2) * D_;
    const ull* WOt = g_WT2 + 3 * (D_ / 2) * D_;
    const ull* W1t = g_WT2 + 4 * (D_ / 2) * D_;
    const ull* W2t = g_WT2 + 5 * (D_ / 2) * D_;
    const ull* WSt = g_WT2 + 6 * (D_ / 2) * D_;

    // ---- flags + new_mask output ----
    if (tid < TM) {
        int m = tid;
        long g = base + m;
        float sc = scores[g];
        float sv = (sc > 0.f) ? 1.f : 0.f;
        unsigned int mw[L_];
#pragma unroll
        for (int l = 0; l < L_; l++) mw[l] = maskw[g * L_ + l];
        float valid = (mw[L_ - 1] == 0u) ? 1.f : 0.f;
        sSaved[m] = sv;
        sValid[m] = valid;
#pragma unroll
        for (int l = 0; l < L_; l++)
            sKpm[m * L_ + l] = (valid > 0.5f && mw[l] != 0u) ? 1.f : 0.f;
#pragma unroll
        for (int l = 0; l < L_; l++) {
            float om;
            if (sv > 0.5f)
                om = (l < L_ - 1) ? ((mw[l + 1] != 0u) ? 1.f : 0.f) : 0.f;
            else
                om = (mw[l] != 0u) ? 1.f : 0.f;
            out_mask[g * L_ + l] = om;
        }
    }
    __syncthreads();

    // ---- bank copy-out (all rows except the save-row), also warms L1 for K/V ----
    {
        const float4* gb = reinterpret_cast<const float4*>(bank) + base * (L_ * D_ / 4);
        float4* ob = reinterpret_cast<float4*>(out_bank) + base * (L_ * D_ / 4);
        for (int idx = tid; idx < TM * L_ * D_ / 4; idx += NT) {
            int m = idx >> 8;             // L*D/4 = 256 float4 per track
            int rem = idx & 255;
            int r = rem >> 6;             // D/4 = 64
            bool sv = sSaved[m] > 0.5f;
            float4 v;
            if (sv) {
                if (r == L_ - 1) continue;  // written at the end (save_embed)
                v = __ldg(gb + idx + (D_ / 4));
            } else {
                v = __ldg(gb + idx);
            }
            ob[idx] = v;
        }
    }

    // ---- Q projection -> sQ (alias sB1), biased ----
    float* sQ = sB1;
    {
        float q[8][4];
        gemv84(E + base * D_, D_, WQt, col0, ly, q);
        float4 bq = *reinterpret_cast<const float4*>(bin + col0);
#pragma unroll
        for (int i = 0; i < 8; i++) {
            float4 v = make_float4(q[i][0] + bq.x, q[i][1] + bq.y, q[i][2] + bq.z,
                                   q[i][3] + bq.w);
            *reinterpret_cast<float4*>(sQ + (ly * 8 + i) * SXS + col0) = v;
        }
    }
    // own-thread smem round trip: no sync needed

    // ---- K projections + logits (warp w == head w since HD=32) ----
    {
        float4 bk = *reinterpret_cast<const float4*>(bin + D_ + col0);
        for (int l = 0; l < L_; l++) {
            float kk[8][4];
            gemv84(bank + (base * L_ + l) * D_, L_ * D_, WKt, col0, ly, kk);
#pragma unroll
            for (int i = 0; i < 8; i++) {
                int row = ly * 8 + i;
                float4 qi = *reinterpret_cast<const float4*>(sQ + row * SXS + col0);
                float p = (kk[i][0] + bk.x) * qi.x + (kk[i][1] + bk.y) * qi.y +
                          (kk[i][2] + bk.z) * qi.z + (kk[i][3] + bk.w) * qi.w;
                p += __shfl_xor_sync(0xffffffffu, p, 1);
                p += __shfl_xor_sync(0xffffffffu, p, 2);
                p += __shfl_xor_sync(0xffffffffu, p, 4);
                if (lx == 0) sAttn[(row * H_ + w) * L_ + l] = p;
            }
        }
    }
    __syncthreads();

    // ---- masked softmax over L (one thread per (m,h)) ----
    {
        int m = tid >> 3, hh = tid & 7;
        float* lr = &sAttn[(m * H_ + hh) * L_];
        float lg[L_];
#pragma unroll
        for (int l = 0; l < L_; l++) {
            float v = lr[l] * 0.17677669529663687f;  // 1/sqrt(32)
            if (sKpm[m * L_ + l] > 0.5f) v = -1e9f;
            lg[l] = v;
        }
        float mx = fmaxf(fmaxf(lg[0], lg[1]), fmaxf(lg[2], lg[3]));
        float ssum = 0.f;
#pragma unroll
        for (int l = 0; l < L_; l++) {
            lg[l] = expf(lg[l] - mx);
            ssum += lg[l];
        }
        float inv = 1.f / ssum;
#pragma unroll
        for (int l = 0; l < L_; l++) lr[l] = lg[l] * inv;
    }
    __syncthreads();

    // ---- V projections + attention-weighted context -> sCtx (alias sB1) ----
    float* sCtx = sB1;  // sQ dead after logits
    {
        float4 bv = *reinterpret_cast<const float4*>(bin + 2 * D_ + col0);
        for (int l = 0; l < L_; l++) {
            float vv[8][4];
            gemv84(bank + (base * L_ + l) * D_, L_ * D_, WVt, col0, ly, vv);
#pragma unroll
            for (int i = 0; i < 8; i++) {
                int row = ly * 8 + i;
                float at = sAttn[(row * H_ + w) * L_ + l];
                float4 prev;
                if (l == 0)
                    prev = make_float4(0.f, 0.f, 0.f, 0.f);
                else
                    prev = *reinterpret_cast<const float4*>(sCtx + row * SXS + col0);
                float4 v = make_float4(prev.x + at * vv[i][0], prev.y + at * vv[i][1],
                                       prev.z + at * vv[i][2], prev.w + at * vv[i][3]);
                if (l == L_ - 1) {  // softmax sums to 1 -> add V bias once
                    v.x += bv.x; v.y += bv.y; v.z += bv.z; v.w += bv.w;
                }
                *reinterpret_cast<float4*>(sCtx + row * SXS + col0) = v;
            }
        }
    }
    __syncthreads();

    // ---- out-proj + residual -> sX ----
    {
        float ao[8][4];
        gemv84(sCtx, SXS, WOt, col0, ly, ao);
        float4 bo = *reinterpret_cast<const float4*>(bout + col0);
#pragma unroll
        for (int i = 0; i < 8; i++) {
            int row = ly * 8 + i;
            float4 e = __ldg(reinterpret_cast<const float4*>(E + (base + row) * D_ + col0));
            float4 v = make_float4(ao[i][0] + bo.x + e.x, ao[i][1] + bo.y + e.y,
                                   ao[i][2] + bo.z + e.z, ao[i][3] + bo.w + e.w);
            *reinterpret_cast<float4*>(sX + row * SXS + col0) = v;
        }
    }
    __syncthreads();

    layernorm_inplace(sX, g1, be1, smu, srstd);

    // ---- FFN: fc1 -> relu -> sH (alias sB1); fc2 -> residual into sX ----
    float* sH = sB1;
    {
        float ha[8][4];
        gemv84(sX, SXS, W1t, col0, ly, ha);
        float4 bb = *reinterpret_cast<const float4*>(b1 + col0);
#pragma unroll
        for (int i = 0; i < 8; i++) {
            int row = ly * 8 + i;
            float4 v = make_float4(fmaxf(ha[i][0] + bb.x, 0.f), fmaxf(ha[i][1] + bb.y, 0.f),
                                   fmaxf(ha[i][2] + bb.z, 0.f), fmaxf(ha[i][3] + bb.w, 0.f));
            *reinterpret_cast<float4*>(sH + row * SXS + col0) = v;
        }
    }
    __syncthreads();
    {
        float ea[8][4];
        gemv84(sH, SXS, W2t, col0, ly, ea);
        float4 bb = *reinterpret_cast<const float4*>(b2 + col0);
#pragma unroll
        for (int i = 0; i < 8; i++) {
            int row = ly * 8 + i;
            float4 prev = *reinterpret_cast<const float4*>(sX + row * SXS + col0);
            float4 v = make_float4(prev.x + ea[i][0] + bb.x, prev.y + ea[i][1] + bb.y,
                                   prev.z + ea[i][2] + bb.z, prev.w + ea[i][3] + bb.w);
            *reinterpret_cast<float4*>(sX + row * SXS + col0) = v;
        }
    }
    __syncthreads();

    layernorm_inplace(sX, g2, be2, smu, srstd);

    // ---- select: invalid rows keep original embedding (col-mapped) ----
    {
        const int o = tid;
#pragma unroll
        for (int m = 0; m < TM; m++)
            if (sValid[m] < 0.5f) sX[m * SXS + o] = __ldg(E + (base + m) * D_ + o);
    }
    __syncthreads();

    // ---- write new_emb ----
    {
        float4* oe = reinterpret_cast<float4*>(out_emb) + base * (D_ / 4);
        for (int idx = tid; idx < TM * D_ / 4; idx += NT) {
            int m = idx >> 6, c = idx & 63;
            oe[idx] = *reinterpret_cast<const float4*>(sX + m * SXS + c * 4);
        }
    }

    // ---- save projection -> new_bank last row where saved ----
    {
        float sa[8][4];
        gemv84(sX, SXS, WSt, col0, ly, sa);
        float4 bb = *reinterpret_cast<const float4*>(bsave + col0);
#pragma unroll
        for (int i = 0; i < 8; i++) {
            int row = ly * 8 + i;
            if (sSaved[row] > 0.5f) {
                float4 v = make_float4(sa[i][0] + bb.x, sa[i][1] + bb.y, sa[i][2] + bb.z,
                                       sa[i][3] + bb.w);
                *reinterpret_cast<float4*>(out_bank + (base + row) * (L_ * D_) +
                                           (L_ - 1) * D_ + col0) = v;
            }
        }
    }
}

extern "C" void kernel_launch(void* const* d_in, const int* in_sizes, int n_in,
                              void* d_out, int out_size) {
    const float* E = (const float*)d_in[0];
    const float* scores = (const float*)d_in[1];
    const float* bank = (const float*)d_in[2];
    const unsigned int* maskw = (const unsigned int*)d_in[3];
    const float* Wsave = (const float*)d_in[4];
    const float* bsave = (const float*)d_in[5];
    const float* Win = (const float*)d_in[6];
    const float* bin = (const float*)d_in[7];
    const float* Wout = (const float*)d_in[8];
    const float* bout = (const float*)d_in[9];
    const float* W1 = (const float*)d_in[10];
    const float* b1 = (const float*)d_in[11];
    const float* W2 = (const float*)d_in[12];
    const float* b2 = (const float*)d_in[13];
    const float* g1 = (const float*)d_in[14];
    const float* be1 = (const float*)d_in[15];
    const float* g2 = (const float*)d_in[16];
    const float* be2 = (const float*)d_in[17];

    int N = in_sizes[0] / D_;
    float* out = (float*)d_out;
    float* out_emb = out;                              // [N, D]
    float* out_bank = out + (size_t)N * D_;            // [N, L, D]
    float* out_mask = out_bank + (size_t)N * L_ * D_;  // [N, L]

    pack_weights_kernel<<<(7 * (D_ / 2) * D_ + 255) / 256, 256>>>(Win, Wout, W1, W2,
                                                                  Wsave);

    cudaFuncSetAttribute(mb_kernel, cudaFuncAttributeMaxDynamicSharedMemorySize,
                         SMEM_BYTES);
    int blocks = N / TM;  // N % TM == 0 for this dataset (100000 = 3125*32)
    mb_kernel<<<blocks, NT, SMEM_BYTES>>>(E, scores, bank, maskw, bsave, bin, bout, b1,
                                          b2, g1, be1, g2, be2, out_emb, out_bank,
                                          out_mask, N);
}

// round 10
// speedup vs baseline: 2.5528x; 2.5528x over previous
#include <cuda_runtime.h>
#include <cuda_bf16.h>
#include <cstdint>

typedef unsigned int u32;

#define DKf 256
#define NRW 64
#define NT 256
#define AS 264    // A image row stride (bf16 elems)
#define ASU 132   // A image row stride (u32)
#define XS 264    // sX row stride (floats)

// smem byte offsets
#define SM_AHI 0
#define SM_ALO 33792
#define SM_X 67584
#define SM_ATT 135168
#define SM_MU 143360
#define SM_RS 143616
#define SM_VAL 143872
#define SM_SAV 144128
#define SM_KPM 144384
#define SMEM_SZ 145408

__device__ __forceinline__ u32 smem_u32(const void* p) {
    u32 a;
    asm("{ .reg .u64 t; cvta.to.shared.u64 t, %1; cvt.u32.u64 %0, t; }" : "=r"(a) : "l"(p));
    return a;
}
__device__ __forceinline__ float wred(float v) {
#pragma unroll
    for (int s = 16; s > 0; s >>= 1) v += __shfl_xor_sync(0xffffffffu, v, s);
    return v;
}
// split x into bf16 hi + bf16 residual, packed pairs (lo half = even elem)
__device__ __forceinline__ void split2(float x0, float x1, u32& h, u32& l) {
    u32 hh;
    asm("cvt.rn.bf16x2.f32 %0, %1, %2;" : "=r"(hh) : "f"(x1), "f"(x0));
    float h0 = __uint_as_float(hh << 16);
    float h1 = __uint_as_float(hh & 0xffff0000u);
    asm("cvt.rn.bf16x2.f32 %0, %1, %2;" : "=r"(l) : "f"(x1 - h1), "f"(x0 - h0));
    h = hh;
}

// ---------------- B-fragment prepacked weights ----------------
// [mat][w][ks][lane][16 u32]: u32 0-7 = hi {nt0b0,nt0b1,...,nt3b1}, 8-15 = lo
__device__ u32 g_Bpk[7 * 8 * 16 * 32 * 16];

__global__ void pack_b(const float* __restrict__ Win, const float* __restrict__ Wout,
                       const float* __restrict__ W1, const float* __restrict__ W2,
                       const float* __restrict__ Wsave) {
    int idx = blockIdx.x * blockDim.x + threadIdx.x;
    if (idx >= 7 * 256 * 128) return;
    int mat = idx / (256 * 128);
    int rem = idx - mat * (256 * 128);
    int n = rem >> 7, p = rem & 127;
    const float* src;
    int nrow = n;
    switch (mat) {
        case 0: src = Win; break;
        case 1: src = Win; nrow = n + 256; break;
        case 2: src = Win; nrow = n + 512; break;
        case 3: src = Wout; break;
        case 4: src = W1; break;
        case 5: src = W2; break;
        default: src = Wsave; break;
    }
    float x0 = src[nrow * DKf + 2 * p], x1 = src[nrow * DKf + 2 * p + 1];
    u32 h, l;
    split2(x0, x1, h, l);
    int w = n >> 5, nt = (n >> 3) & 3, lg = n & 7;
    int ks = p >> 3, pm = p & 7, breg = pm >> 2, ls = pm & 3;
    int lane = lg * 4 + ls;
    u32 base = (u32)((((mat * 8 + w) * 16 + ks) * 32 + lane) * 16);
    g_Bpk[base + nt * 2 + breg] = h;
    g_Bpk[base + 8 + nt * 2 + breg] = l;
}

// ---------------- mma / ldmatrix ----------------
__device__ __forceinline__ void mmab(float* d, const u32* a, u32 b0, u32 b1) {
    asm volatile(
        "mma.sync.aligned.m16n8k16.row.col.f32.bf16.bf16.f32 "
        "{%0,%1,%2,%3}, {%4,%5,%6,%7}, {%8,%9}, {%0,%1,%2,%3};"
        : "+f"(d[0]), "+f"(d[1]), "+f"(d[2]), "+f"(d[3])
        : "r"(a[0]), "r"(a[1]), "r"(a[2]), "r"(a[3]), "r"(b0), "r"(b1));
}
#define LDM4(r, adr)                                                     \
    asm volatile("ldmatrix.sync.aligned.m8n8.x4.shared.b16 {%0,%1,%2,%3}, [%4];" \
                 : "=r"((r)[0]), "=r"((r)[1]), "=r"((r)[2]), "=r"((r)[3]) : "r"(adr))

__device__ __forceinline__ void gemm64(u32 aHi, u32 aLo, const uint4* __restrict__ Bw,
                                       int lane, float d[4][4][4]) {
#pragma unroll
    for (int mt = 0; mt < 4; mt++)
#pragma unroll
        for (int nt = 0; nt < 4; nt++)
#pragma unroll
            for (int r = 0; r < 4; r++) d[mt][nt][r] = 0.f;
    const int rsl = lane & 15, kad = (lane >> 4) * 8;
    uint4 bc0 = __ldg(Bw), bc1 = __ldg(Bw + 1), bc2 = __ldg(Bw + 2), bc3 = __ldg(Bw + 3);
#pragma unroll 1
    for (int ks = 0; ks < 16; ks++) {
        uint4 bn0, bn1, bn2, bn3;
        if (ks < 15) {
            const uint4* bp = Bw + (ks + 1) * 128;
            bn0 = __ldg(bp); bn1 = __ldg(bp + 1); bn2 = __ldg(bp + 2); bn3 = __ldg(bp + 3);
        }
        u32 ah[4][4], al[4][4];
#pragma unroll
        for (int mt = 0; mt < 4; mt++) {
            u32 off = ((u32)(mt * 16 + rsl) * AS + (u32)ks * 16 + kad) * 2;
            LDM4(ah[mt], aHi + off);
            LDM4(al[mt], aLo + off);
        }
        u32 bh[8] = {bc0.x, bc0.y, bc0.z, bc0.w, bc1.x, bc1.y, bc1.z, bc1.w};
        u32 bl[8] = {bc2.x, bc2.y, bc2.z, bc2.w, bc3.x, bc3.y, bc3.z, bc3.w};
#pragma unroll
        for (int mt = 0; mt < 4; mt++)
#pragma unroll
            for (int nt = 0; nt < 4; nt++) {
                mmab(d[mt][nt], ah[mt], bh[2 * nt], bh[2 * nt + 1]);
                mmab(d[mt][nt], ah[mt], bl[2 * nt], bl[2 * nt + 1]);
                mmab(d[mt][nt], al[mt], bh[2 * nt], bh[2 * nt + 1]);
            }
        bc0 = bn0; bc1 = bn1; bc2 = bn2; bc3 = bn3;
    }
}

// ---------------- main kernel ----------------
__global__ void __launch_bounds__(NT, 1)
mb_kernel(const float* __restrict__ E, const float* __restrict__ scores,
          const float* __restrict__ bank, const u32* __restrict__ maskw,
          const float* __restrict__ bsave, const float* __restrict__ bin,
          const float* __restrict__ bout, const float* __restrict__ b1,
          const float* __restrict__ b2, const float* __restrict__ g1,
          const float* __restrict__ be1, const float* __restrict__ g2,
          const float* __restrict__ be2, float* __restrict__ out_emb,
          float* __restrict__ out_bank, float* __restrict__ out_mask, int N) {
    extern __shared__ char sm[];
    const u32 smb = smem_u32(sm);
    const u32 aHi = smb + SM_AHI, aLo = smb + SM_ALO;
    u32* hImg = (u32*)(sm + SM_AHI);
    u32* lImg = (u32*)(sm + SM_ALO);
    float* sX = (float*)(sm + SM_X);
    float* sAtt = (float*)(sm + SM_ATT);
    float* smu = (float*)(sm + SM_MU);
    float* srs = (float*)(sm + SM_RS);
    float* sVal = (float*)(sm + SM_VAL);
    float* sSav = (float*)(sm + SM_SAV);
    float* sKpm = (float*)(sm + SM_KPM);

    const int tid = threadIdx.x;
    const int w = tid >> 5, lane = tid & 31;
    const int g = lane >> 2, t4 = lane & 3;
    const int cb = w * 32 + 2 * t4;  // frag col base; cols = cb + nt*8 (+1)
    const long base = (long)blockIdx.x * NRW;
    long nvl = (long)N - base;
    const int nval = nvl > NRW ? NRW : (int)(nvl > 0 ? nvl : 0);

    // builder mapping: thread owns row br, feats [bf, bf+64)
    const int br = tid & 63, bf = (tid >> 6) * 64;
    const bool bok = br < nval;
    u32* hB = hImg + br * ASU + bf / 2;
    u32* lB = lImg + br * ASU + bf / 2;

    const uint4* Bmat[7];
#pragma unroll
    for (int m = 0; m < 7; m++)
        Bmat[m] = (const uint4*)g_Bpk + (size_t)(((m * 8 + w) * 16) * 32 + lane) * 4;

    // ---- flags + mask output ----
    if (tid < NRW) {
        int m = tid;
        if (m < nval) {
            long gg = base + m;
            float sv = (scores[gg] > 0.f) ? 1.f : 0.f;
            u32 mw[4];
#pragma unroll
            for (int l = 0; l < 4; l++) mw[l] = maskw[gg * 4 + l];
            float valid = (mw[3] == 0u) ? 1.f : 0.f;
            sSav[m] = sv; sVal[m] = valid;
#pragma unroll
            for (int l = 0; l < 4; l++)
                sKpm[m * 4 + l] = (valid > 0.5f && mw[l] != 0u) ? 1.f : 0.f;
#pragma unroll
            for (int l = 0; l < 4; l++) {
                float om = (sv > 0.5f) ? ((l < 3) ? ((mw[l + 1] != 0u) ? 1.f : 0.f) : 0.f)
                                       : ((mw[l] != 0u) ? 1.f : 0.f);
                out_mask[gg * 4 + l] = om;
            }
        } else {
            sSav[m] = 0.f; sVal[m] = 0.f;
#pragma unroll
            for (int l = 0; l < 4; l++) sKpm[m * 4 + l] = 0.f;
        }
    }
    __syncthreads();

    // ---- bank copy-out (shift rows; save-row at end) ----
    {
        const float4* gb = (const float4*)bank + base * 256;
        float4* ob = (float4*)out_bank + base * 256;
        for (int idx = tid; idx < NRW * 256; idx += NT) {
            int m = idx >> 8, rem = idx & 255, r = rem >> 6;
            if (m >= nval) continue;
            bool sv = sSav[m] > 0.5f;
            float4 v;
            if (sv) {
                if (r == 3) continue;
                v = __ldg(gb + idx + 64);
            } else v = __ldg(gb + idx);
            ob[idx] = v;
        }
    }

    // ---- build A from E ----
    {
        const float4* src = (const float4*)(E + (size_t)(base + br) * DKf + bf);
#pragma unroll
        for (int q = 0; q < 16; q++) {
            float4 v = bok ? __ldg(src + q) : make_float4(0, 0, 0, 0);
            u32 h0, l0, h1, l1;
            split2(v.x, v.y, h0, l0); split2(v.z, v.w, h1, l1);
            *(uint2*)(hB + 2 * q) = make_uint2(h0, h1);
            *(uint2*)(lB + 2 * q) = make_uint2(l0, l1);
        }
    }
    __syncthreads();

    float d[4][4][4];

    // ---- Q GEMM -> sX (+bq) ----
    gemm64(aHi, aLo, Bmat[0], lane, d);
#pragma unroll
    for (int mt = 0; mt < 4; mt++) {
        int rA = mt * 16 + g, rB = rA + 8;
#pragma unroll
        for (int nt = 0; nt < 4; nt++) {
            int col = cb + nt * 8;
            float2 bq = __ldg((const float2*)(bin + col));
            *(float2*)&sX[rA * XS + col] = make_float2(d[mt][nt][0] + bq.x, d[mt][nt][1] + bq.y);
            *(float2*)&sX[rB * XS + col] = make_float2(d[mt][nt][2] + bq.x, d[mt][nt][3] + bq.y);
        }
    }
    __syncthreads();

    // ---- K pass: 4 GEMMs + logits ----
#pragma unroll 1
    for (int l = 0; l < 4; l++) {
        const float4* src = (const float4*)(bank + ((size_t)(base + br) * 4 + l) * DKf + bf);
#pragma unroll
        for (int q = 0; q < 16; q++) {
            float4 v = bok ? __ldg(src + q) : make_float4(0, 0, 0, 0);
            u32 h0, l0, h1, l1;
            split2(v.x, v.y, h0, l0); split2(v.z, v.w, h1, l1);
            *(uint2*)(hB + 2 * q) = make_uint2(h0, h1);
            *(uint2*)(lB + 2 * q) = make_uint2(l0, l1);
        }
        __syncthreads();
        gemm64(aHi, aLo, Bmat[1], lane, d);
#pragma unroll
        for (int mt = 0; mt < 4; mt++) {
            int rA = mt * 16 + g, rB = rA + 8;
            float pA = 0.f, pB = 0.f;
#pragma unroll
            for (int nt = 0; nt < 4; nt++) {
                int col = cb + nt * 8;
                float2 bk = __ldg((const float2*)(bin + DKf + col));
                float2 qA = *(const float2*)&sX[rA * XS + col];
                float2 qB = *(const float2*)&sX[rB * XS + col];
                pA += (d[mt][nt][0] + bk.x) * qA.x + (d[mt][nt][1] + bk.y) * qA.y;
                pB += (d[mt][nt][2] + bk.x) * qB.x + (d[mt][nt][3] + bk.y) * qB.y;
            }
            pA += __shfl_xor_sync(0xffffffffu, pA, 1);
            pA += __shfl_xor_sync(0xffffffffu, pA, 2);
            pB += __shfl_xor_sync(0xffffffffu, pB, 1);
            pB += __shfl_xor_sync(0xffffffffu, pB, 2);
            if (t4 == 0) {
                sAtt[(rA * 8 + w) * 4 + l] = pA;
                sAtt[(rB * 8 + w) * 4 + l] = pB;
            }
        }
        __syncthreads();
    }

    // ---- softmax (512 entries, 2/thread) ----
#pragma unroll
    for (int t = 0; t < 2; t++) {
        int id = tid + t * NT;
        int rr = id >> 3, hh = id & 7;
        float* lr = sAtt + (rr * 8 + hh) * 4;
        float lg[4];
#pragma unroll
        for (int l = 0; l < 4; l++) {
            float v = lr[l] * 0.17677669529663687f;
            if (sKpm[rr * 4 + l] > 0.5f) v = -1e9f;
            lg[l] = v;
        }
        float mx = fmaxf(fmaxf(lg[0], lg[1]), fmaxf(lg[2], lg[3]));
        float ss = 0.f;
#pragma unroll
        for (int l = 0; l < 4; l++) { lg[l] = expf(lg[l] - mx); ss += lg[l]; }
        float inv = 1.f / ss;
#pragma unroll
        for (int l = 0; l < 4; l++) lr[l] = lg[l] * inv;
    }
    __syncthreads();

    // ---- V pass: 4 GEMMs, ctx accumulated in sX ----
#pragma unroll 1
    for (int l = 0; l < 4; l++) {
        const float4* src = (const float4*)(bank + ((size_t)(base + br) * 4 + l) * DKf + bf);
#pragma unroll
        for (int q = 0; q < 16; q++) {
            float4 v = bok ? __ldg(src + q) : make_float4(0, 0, 0, 0);
            u32 h0, l0, h1, l1;
            split2(v.x, v.y, h0, l0); split2(v.z, v.w, h1, l1);
            *(uint2*)(hB + 2 * q) = make_uint2(h0, h1);
            *(uint2*)(lB + 2 * q) = make_uint2(l0, l1);
        }
        __syncthreads();
        gemm64(aHi, aLo, Bmat[2], lane, d);
#pragma unroll
        for (int mt = 0; mt < 4; mt++) {
            int rA = mt * 16 + g, rB = rA + 8;
            float aA = sAtt[(rA * 8 + w) * 4 + l];
            float aB = sAtt[(rB * 8 + w) * 4 + l];
#pragma unroll
            for (int nt = 0; nt < 4; nt++) {
                int col = cb + nt * 8;
                float2 pA = (l == 0) ? make_float2(0, 0) : *(const float2*)&sX[rA * XS + col];
                float2 pB = (l == 0) ? make_float2(0, 0) : *(const float2*)&sX[rB * XS + col];
                pA.x += aA * d[mt][nt][0]; pA.y += aA * d[mt][nt][1];
                pB.x += aB * d[mt][nt][2]; pB.y += aB * d[mt][nt][3];
                *(float2*)&sX[rA * XS + col] = pA;
                *(float2*)&sX[rB * XS + col] = pB;
            }
        }
        __syncthreads();
    }

    // ---- ctx + bv -> A ----
    {
        const float4* xs = (const float4*)(sX + br * XS + bf);
#pragma unroll
        for (int q = 0; q < 16; q++) {
            float4 v = xs[q];
            float4 bv = __ldg((const float4*)(bin + 2 * DKf + bf) + q);
            v.x += bv.x; v.y += bv.y; v.z += bv.z; v.w += bv.w;
            u32 h0, l0, h1, l1;
            split2(v.x, v.y, h0, l0); split2(v.z, v.w, h1, l1);
            *(uint2*)(hB + 2 * q) = make_uint2(h0, h1);
            *(uint2*)(lB + 2 * q) = make_uint2(l0, l1);
        }
    }
    __syncthreads();

    // ---- out-proj GEMM -> sX (+bout +E) ----
    gemm64(aHi, aLo, Bmat[3], lane, d);
#pragma unroll
    for (int mt = 0; mt < 4; mt++) {
        int rA = mt * 16 + g, rB = rA + 8;
#pragma unroll
        for (int nt = 0; nt < 4; nt++) {
            int col = cb + nt * 8;
            float2 bo = __ldg((const float2*)(bout + col));
            float2 eA = (rA < nval) ? __ldg((const float2*)(E + (size_t)(base + rA) * DKf + col))
                                    : make_float2(0, 0);
            float2 eB = (rB < nval) ? __ldg((const float2*)(E + (size_t)(base + rB) * DKf + col))
                                    : make_float2(0, 0);
            *(float2*)&sX[rA * XS + col] =
                make_float2(d[mt][nt][0] + bo.x + eA.x, d[mt][nt][1] + bo.y + eA.y);
            *(float2*)&sX[rB * XS + col] =
                make_float2(d[mt][nt][2] + bo.x + eB.x, d[mt][nt][3] + bo.y + eB.y);
        }
    }
    __syncthreads();

    // ---- LN1 reduce ----
#pragma unroll
    for (int k = 0; k < 8; k++) {
        int row = w * 8 + k;
        float s = 0.f, s2 = 0.f;
#pragma unroll
        for (int i = lane; i < DKf; i += 32) {
            float v = sX[row * XS + i];
            s += v; s2 += v * v;
        }
        s = wred(s); s2 = wred(s2);
        if (lane == 0) {
            float mu = s * (1.f / DKf);
            smu[row] = mu;
            srs[row] = rsqrtf(s2 * (1.f / DKf) - mu * mu + 1e-5f);
        }
    }
    __syncthreads();

    // ---- LN1 apply (writeback sX) + build A ----
    {
        float mu = smu[br], rr = srs[br];
        float4* xs = (float4*)(sX + br * XS + bf);
#pragma unroll
        for (int q = 0; q < 16; q++) {
            float4 v = xs[q];
            float4 gv = __ldg((const float4*)(g1 + bf) + q);
            float4 bv = __ldg((const float4*)(be1 + bf) + q);
            v.x = (v.x - mu) * rr * gv.x + bv.x;
            v.y = (v.y - mu) * rr * gv.y + bv.y;
            v.z = (v.z - mu) * rr * gv.z + bv.z;
            v.w = (v.w - mu) * rr * gv.w + bv.w;
            xs[q] = v;
            u32 h0, l0, h1, l1;
            split2(v.x, v.y, h0, l0); split2(v.z, v.w, h1, l1);
            *(uint2*)(hB + 2 * q) = make_uint2(h0, h1);
            *(uint2*)(lB + 2 * q) = make_uint2(l0, l1);
        }
    }
    __syncthreads();

    // ---- fc1 GEMM -> relu -> A (frag-direct) ----
    gemm64(aHi, aLo, Bmat[4], lane, d);
    __syncthreads();
#pragma unroll
    for (int mt = 0; mt < 4; mt++) {
        int rA = mt * 16 + g, rB = rA + 8;
#pragma unroll
        for (int nt = 0; nt < 4; nt++) {
            int col = cb + nt * 8;
            u32 cc = (u32)(w * 16 + nt * 4 + t4);
            float2 bb = __ldg((const float2*)(b1 + col));
            u32 h, lo;
            split2(fmaxf(d[mt][nt][0] + bb.x, 0.f), fmaxf(d[mt][nt][1] + bb.y, 0.f), h, lo);
            hImg[rA * ASU + cc] = h; lImg[rA * ASU + cc] = lo;
            split2(fmaxf(d[mt][nt][2] + bb.x, 0.f), fmaxf(d[mt][nt][3] + bb.y, 0.f), h, lo);
            hImg[rB * ASU + cc] = h; lImg[rB * ASU + cc] = lo;
        }
    }
    __syncthreads();

    // ---- fc2 GEMM -> +b2 +residual -> sX ----
    gemm64(aHi, aLo, Bmat[5], lane, d);
#pragma unroll
    for (int mt = 0; mt < 4; mt++) {
        int rA = mt * 16 + g, rB = rA + 8;
#pragma unroll
        for (int nt = 0; nt < 4; nt++) {
            int col = cb + nt * 8;
            float2 bb = __ldg((const float2*)(b2 + col));
            float2 pA = *(const float2*)&sX[rA * XS + col];
            float2 pB = *(const float2*)&sX[rB * XS + col];
            *(float2*)&sX[rA * XS + col] =
                make_float2(pA.x + d[mt][nt][0] + bb.x, pA.y + d[mt][nt][1] + bb.y);
            *(float2*)&sX[rB * XS + col] =
                make_float2(pB.x + d[mt][nt][2] + bb.x, pB.y + d[mt][nt][3] + bb.y);
        }
    }
    __syncthreads();

    // ---- LN2 reduce ----
#pragma unroll
    for (int k = 0; k < 8; k++) {
        int row = w * 8 + k;
        float s = 0.f, s2 = 0.f;
#pragma unroll
        for (int i = lane; i < DKf; i += 32) {
            float v = sX[row * XS + i];
            s += v; s2 += v * v;
        }
        s = wred(s); s2 = wred(s2);
        if (lane == 0) {
            float mu = s * (1.f / DKf);
            smu[row] = mu;
            srs[row] = rsqrtf(s2 * (1.f / DKf) - mu * mu + 1e-5f);
        }
    }
    __syncthreads();

    // ---- LN2 apply + valid-select + write new_emb + build A (save input) ----
    {
        float mu = smu[br], rr = srs[br];
        bool keep = sVal[br] > 0.5f;
        const float4* es = (const float4*)(E + (size_t)(base + br) * DKf + bf);
        float4* oe = (float4*)(out_emb + (size_t)(base + br) * DKf + bf);
        const float4* xs = (const float4*)(sX + br * XS + bf);
#pragma unroll
        for (int q = 0; q < 16; q++) {
            float4 v = xs[q];
            float4 gv = __ldg((const float4*)(g2 + bf) + q);
            float4 bv = __ldg((const float4*)(be2 + bf) + q);
            v.x = (v.x - mu) * rr * gv.x + bv.x;
            v.y = (v.y - mu) * rr * gv.y + bv.y;
            v.z = (v.z - mu) * rr * gv.z + bv.z;
            v.w = (v.w - mu) * rr * gv.w + bv.w;
            if (!keep) v = bok ? __ldg(es + q) : make_float4(0, 0, 0, 0);
            if (bok) oe[q] = v;
            u32 h0, l0, h1, l1;
            split2(v.x, v.y, h0, l0); split2(v.z, v.w, h1, l1);
            *(uint2*)(hB + 2 * q) = make_uint2(h0, h1);
            *(uint2*)(lB + 2 * q) = make_uint2(l0, l1);
        }
    }
    __syncthreads();

    // ---- save GEMM -> +bsave -> out_bank row 3 (saved rows) ----
    gemm64(aHi, aLo, Bmat[6], lane, d);
#pragma unroll
    for (int mt = 0; mt < 4; mt++) {
        int rA = mt * 16 + g, rB = rA + 8;
#pragma unroll
        for (int nt = 0; nt < 4; nt++) {
            int col = cb + nt * 8;
            float2 bs = __ldg((const float2*)(bsave + col));
            if (rA < nval && sSav[rA] > 0.5f)
                *(float2*)(out_bank + (size_t)(base + rA) * 1024 + 768 + col) =
                    make_float2(d[mt][nt][0] + bs.x, d[mt][nt][1] + bs.y);
            if (rB < nval && sSav[rB] > 0.5f)
                *(float2*)(out_bank + (size_t)(base + rB) * 1024 + 768 + col) =
                    make_float2(d[mt][nt][2] + bs.x, d[mt][nt][3] + bs.y);
        }
    }
}

extern "C" void kernel_launch(void* const* d_in, const int* in_sizes, int n_in,
                              void* d_out, int out_size) {
    const float* E = (const float*)d_in[0];
    const float* scores = (const float*)d_in[1];
    const float* bank = (const float*)d_in[2];
    const u32* maskw = (const u32*)d_in[3];
    const float* Wsave = (const float*)d_in[4];
    const float* bsave = (const float*)d_in[5];
    const float* Win = (const float*)d_in[6];
    const float* bin = (const float*)d_in[7];
    const float* Wout = (const float*)d_in[8];
    const float* bout = (const float*)d_in[9];
    const float* W1 = (const float*)d_in[10];
    const float* b1 = (const float*)d_in[11];
    const float* W2 = (const float*)d_in[12];
    const float* b2 = (const float*)d_in[13];
    const float* g1 = (const float*)d_in[14];
    const float* be1 = (const float*)d_in[15];
    const float* g2 = (const float*)d_in[16];
    const float* be2 = (const float*)d_in[17];

    int N = in_sizes[0] / DKf;
    float* out = (float*)d_out;
    float* out_emb = out;
    float* out_bank = out + (size_t)N * DKf;
    float* out_mask = out_bank + (size_t)N * 4 * DKf;

    pack_b<<<(7 * 256 * 128 + 255) / 256, 256>>>(Win, Wout, W1, W2, Wsave);

    cudaFuncSetAttribute(mb_kernel, cudaFuncAttributeMaxDynamicSharedMemorySize, SMEM_SZ);
    int blocks = (N + NRW - 1) / NRW;
    mb_kernel<<<blocks, NT, SMEM_SZ>>>(E, scores, bank, maskw, bsave, bin, bout, b1, b2,
                                       g1, be1, g2, be2, out_emb, out_bank, out_mask, N);
}